// round 3
// baseline (speedup 1.0000x reference)
#include <cuda_runtime.h>
#include <math.h>

// Problem constants
constexpr int B_  = 2;
constexpr int S_  = 2048;
constexpr int D_  = 2048;
constexpr int H_  = 16;
constexpr int HD_ = 128;

// Scratch (device globals: no allocation allowed)
__device__ float g_q  [(size_t)B_ * S_ * D_];   // [B,S,D]  (== [B,S,H,HD])
__device__ float g_k  [(size_t)B_ * S_ * HD_];  // [B,S,HD]
__device__ float g_v  [(size_t)B_ * S_ * HD_];  // [B,S,HD]
__device__ float g_att[(size_t)B_ * S_ * D_];   // [B,S,H,HD] flattened

// ---------------------------------------------------------------------------
// SGEMM: C[M,N] = A[M,K] @ W[K,N] + bias[N]
// BM=BN=128, BK=8, 256 threads, 8x8 microtile (split quadrants for
// conflict-free LDS.128 fragment loads). blockIdx.z selects (W0,b0,C0) vs
// (W1,b1,C1) so K and V projections run in one launch.
// Requires: M % 128 == 0, N % 128 == 0 (or N == 128), K % 8 == 0.
// ---------------------------------------------------------------------------
__global__ __launch_bounds__(256, 2)
void sgemm128(const float* __restrict__ A,
              const float* __restrict__ W0, const float* __restrict__ bias0, float* __restrict__ C0,
              const float* __restrict__ W1, const float* __restrict__ bias1, float* __restrict__ C1,
              int N, int K)
{
    const float* W   = (blockIdx.z == 0) ? W0    : W1;
    const float* bia = (blockIdx.z == 0) ? bias0 : bias1;
    float*       C   = (blockIdx.z == 0) ? C0    : C1;

    __shared__ float As[8][132];   // +4 pad: keeps 16B alignment, kills store conflicts
    __shared__ float Bs[8][128];

    const int tid  = threadIdx.x;
    const int row0 = blockIdx.y * 128;
    const int col0 = blockIdx.x * 128;

    // loader mapping
    const int a_row = tid >> 1;          // 0..127
    const int a_col = (tid & 1) * 4;     // 0 or 4
    const int b_row = tid >> 5;          // 0..7
    const int b_col = (tid & 31) * 4;    // 0..124

    // compute mapping (split quadrants: rows {ty*4+i, 64+ty*4+i}, cols likewise)
    const int ty = tid >> 4;             // 0..15
    const int tx = tid & 15;             // 0..15

    float acc[8][8];
#pragma unroll
    for (int i = 0; i < 8; ++i)
#pragma unroll
        for (int j = 0; j < 8; ++j) acc[i][j] = 0.0f;

    const float* Ap = A + (size_t)(row0 + a_row) * K + a_col;
    const float* Wp = W + (size_t)b_row * N + col0 + b_col;

    for (int k0 = 0; k0 < K; k0 += 8) {
        float4 av = *(const float4*)(Ap + k0);
        float4 bv = *(const float4*)(Wp + (size_t)k0 * N);
        As[a_col + 0][a_row] = av.x;
        As[a_col + 1][a_row] = av.y;
        As[a_col + 2][a_row] = av.z;
        As[a_col + 3][a_row] = av.w;
        *(float4*)&Bs[b_row][b_col] = bv;
        __syncthreads();

#pragma unroll
        for (int k = 0; k < 8; ++k) {
            float4 a0 = *(const float4*)&As[k][ty * 4];
            float4 a1 = *(const float4*)&As[k][64 + ty * 4];
            float4 b0 = *(const float4*)&Bs[k][tx * 4];
            float4 b1 = *(const float4*)&Bs[k][64 + tx * 4];
            float ar[8] = {a0.x, a0.y, a0.z, a0.w, a1.x, a1.y, a1.z, a1.w};
            float br[8] = {b0.x, b0.y, b0.z, b0.w, b1.x, b1.y, b1.z, b1.w};
#pragma unroll
            for (int i = 0; i < 8; ++i)
#pragma unroll
                for (int j = 0; j < 8; ++j)
                    acc[i][j] = fmaf(ar[i], br[j], acc[i][j]);
        }
        __syncthreads();
    }

    float4 bb0 = *(const float4*)&bia[col0 + tx * 4];
    float4 bb1 = *(const float4*)&bia[col0 + 64 + tx * 4];
    const float bb[8] = {bb0.x, bb0.y, bb0.z, bb0.w, bb1.x, bb1.y, bb1.z, bb1.w};

#pragma unroll
    for (int i = 0; i < 8; ++i) {
        int r = row0 + ((i < 4) ? (ty * 4 + i) : (64 + ty * 4 + (i - 4)));
        float4 o0 = make_float4(acc[i][0] + bb[0], acc[i][1] + bb[1],
                                acc[i][2] + bb[2], acc[i][3] + bb[3]);
        float4 o1 = make_float4(acc[i][4] + bb[4], acc[i][5] + bb[5],
                                acc[i][6] + bb[6], acc[i][7] + bb[7]);
        *(float4*)&C[(size_t)r * N + col0 + tx * 4]      = o0;
        *(float4*)&C[(size_t)r * N + col0 + 64 + tx * 4] = o1;
    }
}

// ---------------------------------------------------------------------------
// Flash-attention (fp32, online softmax). One block per (q-tile=64, head, batch).
// 256 threads: ty=tid/16 owns rows ty*4..ty*4+3, tx=tid%16 owns score cols
// tx*4..tx*4+3 and output cols {tx*4.., 64+tx*4..}.
// Q and K stored K-transposed in smem so the QK^T inner loop is
// 2x LDS.128 + 16 FFMA per k.
// ---------------------------------------------------------------------------
constexpr int SMEM_FLASH = (128 * 64 + 128 * 64 + 64 * 132 + 64 * 64) * 4; // 115712 B

__global__ __launch_bounds__(256, 2)
void mqa_flash(const float* __restrict__ mask,
               const float* __restrict__ Q,  const float* __restrict__ Kg,
               const float* __restrict__ Vg, float* __restrict__ O)
{
    extern __shared__ float sm[];
    float* Qts = sm;                 // [128][64]   Qts[k][r]
    float* Kts = Qts + 128 * 64;     // [128][64]   Kts[k][c]
    float* Vs  = Kts + 128 * 64;     // [64][132]   Vs[c][d]  (pad 132)
    float* Ps  = Vs  + 64 * 132;     // [64][64]    Ps[r][c]

    const int tid = threadIdx.x;
    const int ty  = tid >> 4;
    const int tx  = tid & 15;
    const int q0  = blockIdx.x * 64;
    const int h   = blockIdx.y;
    const int b   = blockIdx.z;

    const int lrow = tid & 63;          // tile row handled by this loader thread
    const int lcb  = (tid >> 6) * 32;   // 32-col chunk

    // Load Q tile transposed: Qts[k][r] = Q[b, q0+r, h*HD+k]
    {
        const float* qp = Q + ((size_t)(b * S_ + q0 + lrow)) * D_ + h * HD_ + lcb;
#pragma unroll
        for (int u = 0; u < 8; ++u) {
            float4 v = *(const float4*)(qp + u * 4);
            int c = lcb + u * 4;
            Qts[(c + 0) * 64 + lrow] = v.x;
            Qts[(c + 1) * 64 + lrow] = v.y;
            Qts[(c + 2) * 64 + lrow] = v.z;
            Qts[(c + 3) * 64 + lrow] = v.w;
        }
    }

    float m_i[4], l_i[4], o[4][8];
#pragma unroll
    for (int i = 0; i < 4; ++i) {
        m_i[i] = -3.0e38f;
        l_i[i] = 0.0f;
#pragma unroll
        for (int j = 0; j < 8; ++j) o[i][j] = 0.0f;
    }

    const float scale = 0.08838834764831845f;   // 1/sqrt(128)

    for (int kv0 = 0; kv0 < S_; kv0 += 64) {
        // Load K (transposed) and V tiles
        {
            const float* kp = Kg + ((size_t)(b * S_ + kv0 + lrow)) * HD_ + lcb;
            const float* vp = Vg + ((size_t)(b * S_ + kv0 + lrow)) * HD_ + lcb;
#pragma unroll
            for (int u = 0; u < 8; ++u) {
                int c = lcb + u * 4;
                float4 kv4 = *(const float4*)(kp + u * 4);
                Kts[(c + 0) * 64 + lrow] = kv4.x;
                Kts[(c + 1) * 64 + lrow] = kv4.y;
                Kts[(c + 2) * 64 + lrow] = kv4.z;
                Kts[(c + 3) * 64 + lrow] = kv4.w;
                float4 vv4 = *(const float4*)(vp + u * 4);
                *(float4*)&Vs[lrow * 132 + c] = vv4;
            }
        }
        __syncthreads();   // Q (first iter), K, V visible

        // S tile = Q @ K^T  (rows ty*4+i, cols tx*4+j)
        float s[4][4];
#pragma unroll
        for (int i = 0; i < 4; ++i)
#pragma unroll
            for (int j = 0; j < 4; ++j) s[i][j] = 0.0f;

#pragma unroll 8
        for (int k = 0; k < 128; ++k) {
            float4 a  = *(const float4*)&Qts[k * 64 + ty * 4];
            float4 kb = *(const float4*)&Kts[k * 64 + tx * 4];
            float av[4] = {a.x, a.y, a.z, a.w};
            float kv[4] = {kb.x, kb.y, kb.z, kb.w};
#pragma unroll
            for (int i = 0; i < 4; ++i)
#pragma unroll
                for (int j = 0; j < 4; ++j)
                    s[i][j] = fmaf(av[i], kv[j], s[i][j]);
        }

        // scale + additive mask
#pragma unroll
        for (int i = 0; i < 4; ++i) {
            const float* mp = mask + ((size_t)b * S_ + (q0 + ty * 4 + i)) * S_ + kv0 + tx * 4;
            float4 mk = *(const float4*)mp;
            s[i][0] = fmaf(s[i][0], scale, mk.x);
            s[i][1] = fmaf(s[i][1], scale, mk.y);
            s[i][2] = fmaf(s[i][2], scale, mk.z);
            s[i][3] = fmaf(s[i][3], scale, mk.w);
        }

        // online softmax per row (16 lanes share a row -> shfl width 16)
#pragma unroll
        for (int i = 0; i < 4; ++i) {
            float tm = fmaxf(fmaxf(s[i][0], s[i][1]), fmaxf(s[i][2], s[i][3]));
#pragma unroll
            for (int msk = 8; msk >= 1; msk >>= 1)
                tm = fmaxf(tm, __shfl_xor_sync(0xffffffffu, tm, msk, 16));
            float mn = fmaxf(m_i[i], tm);
            float al = __expf(m_i[i] - mn);
            m_i[i] = mn;

            float rs = 0.0f;
#pragma unroll
            for (int j = 0; j < 4; ++j) {
                s[i][j] = __expf(s[i][j] - mn);
                rs += s[i][j];
            }
#pragma unroll
            for (int msk = 8; msk >= 1; msk >>= 1)
                rs += __shfl_xor_sync(0xffffffffu, rs, msk, 16);
            l_i[i] = l_i[i] * al + rs;

#pragma unroll
            for (int j = 0; j < 8; ++j) o[i][j] *= al;

            *(float4*)&Ps[(ty * 4 + i) * 64 + tx * 4] =
                make_float4(s[i][0], s[i][1], s[i][2], s[i][3]);
        }
        __syncthreads();   // Ps visible; all Kts reads done

        // O += P @ V   (output cols: {tx*4+j, 64+tx*4+j})
#pragma unroll 2
        for (int c4 = 0; c4 < 16; ++c4) {
            float4 p0 = *(const float4*)&Ps[(ty * 4 + 0) * 64 + c4 * 4];
            float4 p1 = *(const float4*)&Ps[(ty * 4 + 1) * 64 + c4 * 4];
            float4 p2 = *(const float4*)&Ps[(ty * 4 + 2) * 64 + c4 * 4];
            float4 p3 = *(const float4*)&Ps[(ty * 4 + 3) * 64 + c4 * 4];
            float pr[4][4] = {{p0.x, p0.y, p0.z, p0.w},
                              {p1.x, p1.y, p1.z, p1.w},
                              {p2.x, p2.y, p2.z, p2.w},
                              {p3.x, p3.y, p3.z, p3.w}};
#pragma unroll
            for (int cc = 0; cc < 4; ++cc) {
                int c = c4 * 4 + cc;
                float4 va = *(const float4*)&Vs[c * 132 + tx * 4];
                float4 vb = *(const float4*)&Vs[c * 132 + 64 + tx * 4];
                float vv[8] = {va.x, va.y, va.z, va.w, vb.x, vb.y, vb.z, vb.w};
#pragma unroll
                for (int i = 0; i < 4; ++i)
#pragma unroll
                    for (int j = 0; j < 8; ++j)
                        o[i][j] = fmaf(pr[i][cc], vv[j], o[i][j]);
            }
        }
        __syncthreads();   // PV done before next tile's K/V load
    }

    // finalize: divide by l, write to g_att[b, q0+r, h, :]
#pragma unroll
    for (int i = 0; i < 4; ++i) {
        float inv = 1.0f / l_i[i];
        size_t base = ((size_t)(b * S_ + q0 + ty * 4 + i)) * D_ + h * HD_;
        float4 o0 = make_float4(o[i][0] * inv, o[i][1] * inv, o[i][2] * inv, o[i][3] * inv);
        float4 o1 = make_float4(o[i][4] * inv, o[i][5] * inv, o[i][6] * inv, o[i][7] * inv);
        *(float4*)&O[base + tx * 4]      = o0;
        *(float4*)&O[base + 64 + tx * 4] = o1;
    }
}

// ---------------------------------------------------------------------------
extern "C" void kernel_launch(void* const* d_in, const int* in_sizes, int n_in,
                              void* d_out, int out_size)
{
    (void)in_sizes; (void)n_in; (void)out_size;
    const float* x    = (const float*)d_in[0];
    const float* mask = (const float*)d_in[1];
    const float* wq_w = (const float*)d_in[2];
    const float* wq_b = (const float*)d_in[3];
    const float* wk_w = (const float*)d_in[4];
    const float* wk_b = (const float*)d_in[5];
    const float* wv_w = (const float*)d_in[6];
    const float* wv_b = (const float*)d_in[7];
    const float* wo_w = (const float*)d_in[8];
    const float* wo_b = (const float*)d_in[9];
    float* out = (float*)d_out;

    float *qb, *kb, *vb, *ab;
    cudaGetSymbolAddress((void**)&qb, g_q);
    cudaGetSymbolAddress((void**)&kb, g_k);
    cudaGetSymbolAddress((void**)&vb, g_v);
    cudaGetSymbolAddress((void**)&ab, g_att);

    cudaFuncSetAttribute(mqa_flash, cudaFuncAttributeMaxDynamicSharedMemorySize, SMEM_FLASH);

    dim3 blk(256);
    // Q = x @ wq + bq           [4096,2048] x [2048,2048]
    sgemm128<<<dim3(16, 32, 1), blk>>>(x, wq_w, wq_b, qb, wq_w, wq_b, qb, D_, D_);
    // K,V = x @ wk/wv + b       [4096,2048] x [2048,128], one launch (z selects)
    sgemm128<<<dim3(1, 32, 2), blk>>>(x, wk_w, wk_b, kb, wv_w, wv_b, vb, HD_, D_);
    // attention
    mqa_flash<<<dim3(S_ / 64, H_, B_), blk, SMEM_FLASH>>>(mask, qb, kb, vb, ab);
    // out = att @ wo + bo
    sgemm128<<<dim3(16, 32, 1), blk>>>(ab, wo_w, wo_b, out, wo_w, wo_b, out, D_, D_);
}

// round 4
// speedup vs baseline: 1.0000x; 1.0000x over previous
#include <cuda_runtime.h>
#include <math.h>

// Problem constants
constexpr int B_  = 2;
constexpr int S_  = 2048;
constexpr int D_  = 2048;
constexpr int H_  = 16;
constexpr int HD_ = 128;

// Scratch (device globals: no allocation allowed)
__device__ float g_q  [(size_t)B_ * S_ * D_];   // [B,S,D]  (== [B,S,H,HD])
__device__ float g_k  [(size_t)B_ * S_ * HD_];  // [B,S,HD]
__device__ float g_v  [(size_t)B_ * S_ * HD_];  // [B,S,HD]
__device__ float g_att[(size_t)B_ * S_ * D_];   // [B,S,H,HD] flattened

// ---------------------------------------------------------------------------
// SGEMM: C[M,N] = A[M,K] @ W[K,N] + bias[N]
// BM=BN=128, BK=8, 256 threads, 8x8 microtile (split quadrants for
// conflict-free LDS.128 fragment loads). blockIdx.z selects (W0,b0,C0) vs
// (W1,b1,C1) so K and V projections run in one launch.
// Requires: M % 128 == 0, N % 128 == 0 (or N == 128), K % 8 == 0.
// ---------------------------------------------------------------------------
__global__ __launch_bounds__(256, 2)
void sgemm128(const float* __restrict__ A,
              const float* __restrict__ W0, const float* __restrict__ bias0, float* __restrict__ C0,
              const float* __restrict__ W1, const float* __restrict__ bias1, float* __restrict__ C1,
              int N, int K)
{
    const float* W   = (blockIdx.z == 0) ? W0    : W1;
    const float* bia = (blockIdx.z == 0) ? bias0 : bias1;
    float*       C   = (blockIdx.z == 0) ? C0    : C1;

    __shared__ float As[8][132];   // +4 pad: keeps 16B alignment, kills store conflicts
    __shared__ float Bs[8][128];

    const int tid  = threadIdx.x;
    const int row0 = blockIdx.y * 128;
    const int col0 = blockIdx.x * 128;

    // loader mapping
    const int a_row = tid >> 1;          // 0..127
    const int a_col = (tid & 1) * 4;     // 0 or 4
    const int b_row = tid >> 5;          // 0..7
    const int b_col = (tid & 31) * 4;    // 0..124

    // compute mapping (split quadrants: rows {ty*4+i, 64+ty*4+i}, cols likewise)
    const int ty = tid >> 4;             // 0..15
    const int tx = tid & 15;             // 0..15

    float acc[8][8];
#pragma unroll
    for (int i = 0; i < 8; ++i)
#pragma unroll
        for (int j = 0; j < 8; ++j) acc[i][j] = 0.0f;

    const float* Ap = A + (size_t)(row0 + a_row) * K + a_col;
    const float* Wp = W + (size_t)b_row * N + col0 + b_col;

    for (int k0 = 0; k0 < K; k0 += 8) {
        float4 av = *(const float4*)(Ap + k0);
        float4 bv = *(const float4*)(Wp + (size_t)k0 * N);
        As[a_col + 0][a_row] = av.x;
        As[a_col + 1][a_row] = av.y;
        As[a_col + 2][a_row] = av.z;
        As[a_col + 3][a_row] = av.w;
        *(float4*)&Bs[b_row][b_col] = bv;
        __syncthreads();

#pragma unroll
        for (int k = 0; k < 8; ++k) {
            float4 a0 = *(const float4*)&As[k][ty * 4];
            float4 a1 = *(const float4*)&As[k][64 + ty * 4];
            float4 b0 = *(const float4*)&Bs[k][tx * 4];
            float4 b1 = *(const float4*)&Bs[k][64 + tx * 4];
            float ar[8] = {a0.x, a0.y, a0.z, a0.w, a1.x, a1.y, a1.z, a1.w};
            float br[8] = {b0.x, b0.y, b0.z, b0.w, b1.x, b1.y, b1.z, b1.w};
#pragma unroll
            for (int i = 0; i < 8; ++i)
#pragma unroll
                for (int j = 0; j < 8; ++j)
                    acc[i][j] = fmaf(ar[i], br[j], acc[i][j]);
        }
        __syncthreads();
    }

    float4 bb0 = *(const float4*)&bia[col0 + tx * 4];
    float4 bb1 = *(const float4*)&bia[col0 + 64 + tx * 4];
    const float bb[8] = {bb0.x, bb0.y, bb0.z, bb0.w, bb1.x, bb1.y, bb1.z, bb1.w};

#pragma unroll
    for (int i = 0; i < 8; ++i) {
        int r = row0 + ((i < 4) ? (ty * 4 + i) : (64 + ty * 4 + (i - 4)));
        float4 o0 = make_float4(acc[i][0] + bb[0], acc[i][1] + bb[1],
                                acc[i][2] + bb[2], acc[i][3] + bb[3]);
        float4 o1 = make_float4(acc[i][4] + bb[4], acc[i][5] + bb[5],
                                acc[i][6] + bb[6], acc[i][7] + bb[7]);
        *(float4*)&C[(size_t)r * N + col0 + tx * 4]      = o0;
        *(float4*)&C[(size_t)r * N + col0 + 64 + tx * 4] = o1;
    }
}

// ---------------------------------------------------------------------------
// Flash-attention (fp32, online softmax). One block per (q-tile=64, head, batch).
// 256 threads: ty=tid/16 owns rows ty*4..ty*4+3, tx=tid%16 owns score cols
// tx*4..tx*4+3 and output cols {tx*4.., 64+tx*4..}.
// Q and K stored K-transposed in smem so the QK^T inner loop is
// 2x LDS.128 + 16 FFMA per k.
// ---------------------------------------------------------------------------
constexpr int SMEM_FLASH = (128 * 64 + 128 * 64 + 64 * 132 + 64 * 64) * 4; // 115712 B

__global__ __launch_bounds__(256, 2)
void mqa_flash(const float* __restrict__ mask,
               const float* __restrict__ Q,  const float* __restrict__ Kg,
               const float* __restrict__ Vg, float* __restrict__ O)
{
    extern __shared__ float sm[];
    float* Qts = sm;                 // [128][64]   Qts[k][r]
    float* Kts = Qts + 128 * 64;     // [128][64]   Kts[k][c]
    float* Vs  = Kts + 128 * 64;     // [64][132]   Vs[c][d]  (pad 132)
    float* Ps  = Vs  + 64 * 132;     // [64][64]    Ps[r][c]

    const int tid = threadIdx.x;
    const int ty  = tid >> 4;
    const int tx  = tid & 15;
    const int q0  = blockIdx.x * 64;
    const int h   = blockIdx.y;
    const int b   = blockIdx.z;

    const int lrow = tid & 63;          // tile row handled by this loader thread
    const int lcb  = (tid >> 6) * 32;   // 32-col chunk

    // Load Q tile transposed: Qts[k][r] = Q[b, q0+r, h*HD+k]
    {
        const float* qp = Q + ((size_t)(b * S_ + q0 + lrow)) * D_ + h * HD_ + lcb;
#pragma unroll
        for (int u = 0; u < 8; ++u) {
            float4 v = *(const float4*)(qp + u * 4);
            int c = lcb + u * 4;
            Qts[(c + 0) * 64 + lrow] = v.x;
            Qts[(c + 1) * 64 + lrow] = v.y;
            Qts[(c + 2) * 64 + lrow] = v.z;
            Qts[(c + 3) * 64 + lrow] = v.w;
        }
    }

    float m_i[4], l_i[4], o[4][8];
#pragma unroll
    for (int i = 0; i < 4; ++i) {
        m_i[i] = -3.0e38f;
        l_i[i] = 0.0f;
#pragma unroll
        for (int j = 0; j < 8; ++j) o[i][j] = 0.0f;
    }

    const float scale = 0.08838834764831845f;   // 1/sqrt(128)

    for (int kv0 = 0; kv0 < S_; kv0 += 64) {
        // Load K (transposed) and V tiles
        {
            const float* kp = Kg + ((size_t)(b * S_ + kv0 + lrow)) * HD_ + lcb;
            const float* vp = Vg + ((size_t)(b * S_ + kv0 + lrow)) * HD_ + lcb;
#pragma unroll
            for (int u = 0; u < 8; ++u) {
                int c = lcb + u * 4;
                float4 kv4 = *(const float4*)(kp + u * 4);
                Kts[(c + 0) * 64 + lrow] = kv4.x;
                Kts[(c + 1) * 64 + lrow] = kv4.y;
                Kts[(c + 2) * 64 + lrow] = kv4.z;
                Kts[(c + 3) * 64 + lrow] = kv4.w;
                float4 vv4 = *(const float4*)(vp + u * 4);
                *(float4*)&Vs[lrow * 132 + c] = vv4;
            }
        }
        __syncthreads();   // Q (first iter), K, V visible

        // S tile = Q @ K^T  (rows ty*4+i, cols tx*4+j)
        float s[4][4];
#pragma unroll
        for (int i = 0; i < 4; ++i)
#pragma unroll
            for (int j = 0; j < 4; ++j) s[i][j] = 0.0f;

#pragma unroll 8
        for (int k = 0; k < 128; ++k) {
            float4 a  = *(const float4*)&Qts[k * 64 + ty * 4];
            float4 kb = *(const float4*)&Kts[k * 64 + tx * 4];
            float av[4] = {a.x, a.y, a.z, a.w};
            float kv[4] = {kb.x, kb.y, kb.z, kb.w};
#pragma unroll
            for (int i = 0; i < 4; ++i)
#pragma unroll
                for (int j = 0; j < 4; ++j)
                    s[i][j] = fmaf(av[i], kv[j], s[i][j]);
        }

        // scale + additive mask
#pragma unroll
        for (int i = 0; i < 4; ++i) {
            const float* mp = mask + ((size_t)b * S_ + (q0 + ty * 4 + i)) * S_ + kv0 + tx * 4;
            float4 mk = *(const float4*)mp;
            s[i][0] = fmaf(s[i][0], scale, mk.x);
            s[i][1] = fmaf(s[i][1], scale, mk.y);
            s[i][2] = fmaf(s[i][2], scale, mk.z);
            s[i][3] = fmaf(s[i][3], scale, mk.w);
        }

        // online softmax per row (16 lanes share a row -> shfl width 16)
#pragma unroll
        for (int i = 0; i < 4; ++i) {
            float tm = fmaxf(fmaxf(s[i][0], s[i][1]), fmaxf(s[i][2], s[i][3]));
#pragma unroll
            for (int msk = 8; msk >= 1; msk >>= 1)
                tm = fmaxf(tm, __shfl_xor_sync(0xffffffffu, tm, msk, 16));
            float mn = fmaxf(m_i[i], tm);
            float al = __expf(m_i[i] - mn);
            m_i[i] = mn;

            float rs = 0.0f;
#pragma unroll
            for (int j = 0; j < 4; ++j) {
                s[i][j] = __expf(s[i][j] - mn);
                rs += s[i][j];
            }
#pragma unroll
            for (int msk = 8; msk >= 1; msk >>= 1)
                rs += __shfl_xor_sync(0xffffffffu, rs, msk, 16);
            l_i[i] = l_i[i] * al + rs;

#pragma unroll
            for (int j = 0; j < 8; ++j) o[i][j] *= al;

            *(float4*)&Ps[(ty * 4 + i) * 64 + tx * 4] =
                make_float4(s[i][0], s[i][1], s[i][2], s[i][3]);
        }
        __syncthreads();   // Ps visible; all Kts reads done

        // O += P @ V   (output cols: {tx*4+j, 64+tx*4+j})
#pragma unroll 2
        for (int c4 = 0; c4 < 16; ++c4) {
            float4 p0 = *(const float4*)&Ps[(ty * 4 + 0) * 64 + c4 * 4];
            float4 p1 = *(const float4*)&Ps[(ty * 4 + 1) * 64 + c4 * 4];
            float4 p2 = *(const float4*)&Ps[(ty * 4 + 2) * 64 + c4 * 4];
            float4 p3 = *(const float4*)&Ps[(ty * 4 + 3) * 64 + c4 * 4];
            float pr[4][4] = {{p0.x, p0.y, p0.z, p0.w},
                              {p1.x, p1.y, p1.z, p1.w},
                              {p2.x, p2.y, p2.z, p2.w},
                              {p3.x, p3.y, p3.z, p3.w}};
#pragma unroll
            for (int cc = 0; cc < 4; ++cc) {
                int c = c4 * 4 + cc;
                float4 va = *(const float4*)&Vs[c * 132 + tx * 4];
                float4 vb = *(const float4*)&Vs[c * 132 + 64 + tx * 4];
                float vv[8] = {va.x, va.y, va.z, va.w, vb.x, vb.y, vb.z, vb.w};
#pragma unroll
                for (int i = 0; i < 4; ++i)
#pragma unroll
                    for (int j = 0; j < 8; ++j)
                        o[i][j] = fmaf(pr[i][cc], vv[j], o[i][j]);
            }
        }
        __syncthreads();   // PV done before next tile's K/V load
    }

    // finalize: divide by l, write to g_att[b, q0+r, h, :]
#pragma unroll
    for (int i = 0; i < 4; ++i) {
        float inv = 1.0f / l_i[i];
        size_t base = ((size_t)(b * S_ + q0 + ty * 4 + i)) * D_ + h * HD_;
        float4 o0 = make_float4(o[i][0] * inv, o[i][1] * inv, o[i][2] * inv, o[i][3] * inv);
        float4 o1 = make_float4(o[i][4] * inv, o[i][5] * inv, o[i][6] * inv, o[i][7] * inv);
        *(float4*)&O[base + tx * 4]      = o0;
        *(float4*)&O[base + 64 + tx * 4] = o1;
    }
}

// ---------------------------------------------------------------------------
extern "C" void kernel_launch(void* const* d_in, const int* in_sizes, int n_in,
                              void* d_out, int out_size)
{
    (void)in_sizes; (void)n_in; (void)out_size;
    const float* x    = (const float*)d_in[0];
    const float* mask = (const float*)d_in[1];
    const float* wq_w = (const float*)d_in[2];
    const float* wq_b = (const float*)d_in[3];
    const float* wk_w = (const float*)d_in[4];
    const float* wk_b = (const float*)d_in[5];
    const float* wv_w = (const float*)d_in[6];
    const float* wv_b = (const float*)d_in[7];
    const float* wo_w = (const float*)d_in[8];
    const float* wo_b = (const float*)d_in[9];
    float* out = (float*)d_out;

    float *qb, *kb, *vb, *ab;
    cudaGetSymbolAddress((void**)&qb, g_q);
    cudaGetSymbolAddress((void**)&kb, g_k);
    cudaGetSymbolAddress((void**)&vb, g_v);
    cudaGetSymbolAddress((void**)&ab, g_att);

    cudaFuncSetAttribute(mqa_flash, cudaFuncAttributeMaxDynamicSharedMemorySize, SMEM_FLASH);

    dim3 blk(256);
    // Q = x @ wq + bq           [4096,2048] x [2048,2048]
    sgemm128<<<dim3(16, 32, 1), blk>>>(x, wq_w, wq_b, qb, wq_w, wq_b, qb, D_, D_);
    // K,V = x @ wk/wv + b       [4096,2048] x [2048,128], one launch (z selects)
    sgemm128<<<dim3(1, 32, 2), blk>>>(x, wk_w, wk_b, kb, wv_w, wv_b, vb, HD_, D_);
    // attention
    mqa_flash<<<dim3(S_ / 64, H_, B_), blk, SMEM_FLASH>>>(mask, qb, kb, vb, ab);
    // out = att @ wo + bo
    sgemm128<<<dim3(16, 32, 1), blk>>>(ab, wo_w, wo_b, out, wo_w, wo_b, out, D_, D_);
}